// round 4
// baseline (speedup 1.0000x reference)
#include <cuda_runtime.h>

// Sizes (fixed by the problem)
#define BB   32
#define TT   128
#define INN  128
#define HH   256
#define G4   1024   // 4*HH
#define OO   128

// ---------------- scratch (__device__ globals: no runtime allocation) -------
static __device__ float g_xg[BB * TT * G4];   // xg = x@W_ih^T + b_ih + b_hh   (16.8 MB)
static __device__ float g_bx[BB * TT * HH];   // Bx = x@W_B^T + b_B           (4.2 MB)
static __device__ float g_whh_p[G4 * HH];     // W_hh repacked for coalesced thread-per-row
static __device__ float g_wa_p[HH * HH];      // W_A repacked for (row=tid>>2, quarter=tid&3)
static __device__ float g_wc_p[OO * HH];      // W_C repacked for (row=tid>>3, eighth=tid&7)

typedef unsigned long long ull;

__device__ __forceinline__ ull ffma2(ull c, ull a, ull b) {
    ull d;
    asm("fma.rn.f32x2 %0, %1, %2, %3;" : "=l"(d) : "l"(a), "l"(b), "l"(c));
    return d;
}
__device__ __forceinline__ float hsum2(ull v) {
    return __uint_as_float((unsigned)(v & 0xffffffffull)) +
           __uint_as_float((unsigned)(v >> 32));
}

// ---------------- precompute GEMMs: C[4096,N] = X[4096,128] @ W[N,128]^T + bias (+bias2)
template <int N, int DEST>
__global__ __launch_bounds__(256) void gemm_bias(
    const float* __restrict__ X, const float* __restrict__ W,
    const float* __restrict__ bias, const float* __restrict__ bias2)
{
    constexpr int K = INN;  // 128
    __shared__ float As[32][64];  // k-major
    __shared__ float Bs[32][64];
    float* C = (DEST == 0) ? g_xg : g_bx;

    const int bm = blockIdx.y * 64, bn = blockIdx.x * 64;
    const int tid = threadIdx.x;
    const int tx = tid & 15, ty = tid >> 4;

    float acc[4][4];
#pragma unroll
    for (int r = 0; r < 4; r++)
#pragma unroll
        for (int c = 0; c < 4; c++) acc[r][c] = 0.f;

    for (int k0 = 0; k0 < K; k0 += 32) {
#pragma unroll
        for (int q = 0; q < 2; q++) {
            int i = tid * 2 + q;          // 0..511
            int row = i >> 3;             // 0..63
            int kc = (i & 7) * 4;         // 0..28
            float4 a = *(const float4*)(X + (size_t)(bm + row) * K + k0 + kc);
            As[kc + 0][row] = a.x; As[kc + 1][row] = a.y;
            As[kc + 2][row] = a.z; As[kc + 3][row] = a.w;
            float4 b = *(const float4*)(W + (size_t)(bn + row) * K + k0 + kc);
            Bs[kc + 0][row] = b.x; Bs[kc + 1][row] = b.y;
            Bs[kc + 2][row] = b.z; Bs[kc + 3][row] = b.w;
        }
        __syncthreads();
#pragma unroll
        for (int kk = 0; kk < 32; kk++) {
            float4 av = *(const float4*)&As[kk][ty * 4];
            float4 bv = *(const float4*)&Bs[kk][tx * 4];
            float ar[4] = {av.x, av.y, av.z, av.w};
            float br[4] = {bv.x, bv.y, bv.z, bv.w};
#pragma unroll
            for (int r = 0; r < 4; r++)
#pragma unroll
                for (int c = 0; c < 4; c++) acc[r][c] += ar[r] * br[c];
        }
        __syncthreads();
    }

    float bc[4];
#pragma unroll
    for (int c = 0; c < 4; c++) {
        bc[c] = bias[bn + tx * 4 + c];
        if (bias2) bc[c] += bias2[bn + tx * 4 + c];
    }
#pragma unroll
    for (int r = 0; r < 4; r++) {
        float4 o;
        o.x = acc[r][0] + bc[0]; o.y = acc[r][1] + bc[1];
        o.z = acc[r][2] + bc[2]; o.w = acc[r][3] + bc[3];
        *(float4*)(C + (size_t)(bm + ty * 4 + r) * N + bn + tx * 4) = o;
    }
}

// ---------------- weight repack for coalesced recurrent loads ---------------
// g_whh_p[(k4*1024 + g)*4 + m] = W_hh[g*256 + 4*k4 + m]        (k4: 0..63)
// g_wa_p [(k *1024 + t)*4 + m] = W_A [(t>>2)*256 + (t&3)*64 + 4k + m]  (k: 0..15)
// g_wc_p [(k *1024 + t)*4 + m] = W_C [(t>>3)*256 + (t&7)*32 + 4k + m]  (k: 0..7)
__global__ void pack_weights(const float* __restrict__ W_hh,
                             const float* __restrict__ W_A,
                             const float* __restrict__ W_C)
{
    int i = blockIdx.x * blockDim.x + threadIdx.x;
    if (i < G4 * HH) {
        int m = i & 3, gk = i >> 2;
        int g = gk & 1023, k4 = gk >> 10;
        g_whh_p[i] = W_hh[g * HH + k4 * 4 + m];
    }
    if (i < HH * HH) {
        int m = i & 3, kt = i >> 2;
        int tp = kt & 1023, k = kt >> 10;
        g_wa_p[i] = W_A[(tp >> 2) * HH + (tp & 3) * 64 + k * 4 + m];
    }
    if (i < OO * HH) {
        int m = i & 3, kt = i >> 2;
        int tp = kt & 1023, k = kt >> 10;
        g_wc_p[i] = W_C[(tp >> 3) * HH + (tp & 7) * 32 + k * 4 + m];
    }
}

// ---------------- sequential fused LSTM + CfC kernel: 1 CTA per batch -------
__global__ __launch_bounds__(1024, 1) void seq_kernel(
    const float* __restrict__ timespans,  // [B,T]
    const float* __restrict__ tau,        // [H]
    const float* __restrict__ sigma,      // [H]
    const float* __restrict__ b_C,        // [OUT]
    float* __restrict__ out)              // [B,T,OUT]
{
    __shared__ __align__(16) float sh_h[HH];     // LSTM hidden
    __shared__ __align__(16) float sh_u[HH];     // ODE state
    __shared__ __align__(16) float sh_us[HH];    // u / tau
    __shared__ __align__(16) float sh_fu[HH];    // tanh(u / sigma)
    __shared__ __align__(16) float sh_g[G4];     // gate pre-activations
    __shared__ __align__(16) float sh_v1[HH];    // ts * A_eff @ u
    __shared__ __align__(16) float sh_v1s[HH];   // v1 / tau
    __shared__ __align__(16) float sh_drv[HH];   // W_A @ f_u
    __shared__ __align__(16) float sh_v2[HH];    // A_eff @ v1
    __shared__ __align__(16) float sh_itau[HH];
    __shared__ __align__(16) float sh_isig[HH];

    const int b = blockIdx.x;
    const int tid = threadIdx.x;

    if (tid < HH) {
        sh_h[tid] = 0.f; sh_u[tid] = 0.f; sh_us[tid] = 0.f; sh_fu[tid] = 0.f;
        sh_itau[tid] = 1.0f / tau[tid];
        sh_isig[tid] = 1.0f / sigma[tid];
    }
    float c_st = 0.f;
    __syncthreads();

    const int r4 = tid >> 2, q4 = tid & 3;   // W_A row / quarter of j-range
    const int r8 = tid >> 3, q8 = tid & 7;   // W_C row / eighth of j-range
    const float it_r = sh_itau[r4];
    const float bCr  = b_C[r8];

    const ulonglong2* whh = (const ulonglong2*)g_whh_p + tid;
    const ulonglong2* wap = (const ulonglong2*)g_wa_p + tid;
    const ulonglong2* wcp = (const ulonglong2*)g_wc_p + tid;
    const ulonglong2* hh2 = (const ulonglong2*)sh_h;
    const ulonglong2* us2 = (const ulonglong2*)(sh_us + (q4 << 6));
    const ulonglong2* fu2 = (const ulonglong2*)(sh_fu + (q4 << 6));
    const ulonglong2* v1s2 = (const ulonglong2*)(sh_v1s + (q4 << 6));
    const ulonglong2* uu2 = (const ulonglong2*)(sh_u + (q8 << 5));

    const float* xg_b = g_xg + (size_t)b * TT * G4 + tid;
    const float* bx_b = g_bx + (size_t)b * TT * HH + tid;
    const float* ts_b = timespans + b * TT;
    float* out_b = out + (size_t)b * TT * OO;

    for (int t = 0; t < TT; t++) {
        const float ts = ts_b[t];

        // -------- Phase A: gate pre-activations (all 1024 threads, 1 row each)
        {
            ull a0 = 0ull, a1 = 0ull;
#pragma unroll 4
            for (int k = 0; k < 64; k++) {
                ulonglong2 wv = whh[k * 1024];   // coalesced LDG.128
                ulonglong2 hv = hh2[k];          // broadcast LDS.128
                a0 = ffma2(a0, wv.x, hv.x);
                a1 = ffma2(a1, wv.y, hv.y);
            }
            sh_g[tid] = xg_b[(size_t)t * G4] + hsum2(a0) + hsum2(a1);
        }
        // -------- Phase A2: v1 = ts*A_eff@u and drive = W_A@f_u (shared weight read)
        {
            ull av = 0ull, ad = 0ull;
#pragma unroll
            for (int k = 0; k < 16; k++) {
                ulonglong2 wv = wap[k * 1024];
                ulonglong2 uv = us2[k];
                ulonglong2 fv = fu2[k];
                av = ffma2(av, wv.x, uv.x); av = ffma2(av, wv.y, uv.y);
                ad = ffma2(ad, wv.x, fv.x); ad = ffma2(ad, wv.y, fv.y);
            }
            float v = hsum2(av), d = hsum2(ad);
            v += __shfl_down_sync(0xffffffffu, v, 2, 4);
            v += __shfl_down_sync(0xffffffffu, v, 1, 4);
            d += __shfl_down_sync(0xffffffffu, d, 2, 4);
            d += __shfl_down_sync(0xffffffffu, d, 1, 4);
            if (q4 == 0) {
                float vv = ts * v;
                sh_v1[r4] = vv;
                sh_v1s[r4] = vv * it_r;
                sh_drv[r4] = d;
            }
        }
        __syncthreads();

        // -------- Phase B: LSTM cell update (tid<256) + v2 = A_eff@v1 (all)
        float bb = 0.f;
        if (tid < HH) {
            float gi = sh_g[tid];
            float gf = sh_g[HH + tid];
            float gg = sh_g[2 * HH + tid];
            float go = sh_g[3 * HH + tid];
            float si = 1.f / (1.f + __expf(-gi));
            float sf = 1.f / (1.f + __expf(-gf));
            float so = 1.f / (1.f + __expf(-go));
            c_st = sf * c_st + si * tanhf(gg);
            bb = so * tanhf(c_st);
            sh_h[tid] = bb;
        }
        {
            ull av = 0ull;
#pragma unroll
            for (int k = 0; k < 16; k++) {
                ulonglong2 wv = wap[k * 1024];
                ulonglong2 xv = v1s2[k];
                av = ffma2(av, wv.x, xv.x);
                av = ffma2(av, wv.y, xv.y);
            }
            float v = hsum2(av);
            v += __shfl_down_sync(0xffffffffu, v, 2, 4);
            v += __shfl_down_sync(0xffffffffu, v, 1, 4);
            if (q4 == 0) sh_v2[r4] = v;
        }
        __syncthreads();

        // -------- Phase C: ODE state update (tid<256)
        if (tid < HH) {
            float bx = bx_b[(size_t)t * HH];
            float un = sh_u[tid] + sh_v1[tid] + 0.5f * ts * sh_v2[tid]
                     + ts * (sh_drv[tid] + bx) * sh_itau[tid] + bb;
            sh_u[tid] = un;
            sh_us[tid] = un * sh_itau[tid];
            sh_fu[tid] = tanhf(un * sh_isig[tid]);
        }
        __syncthreads();

        // -------- Phase D: y = u_new @ W_C^T + b_C  (128 rows x 8 lanes)
        {
            ull ay = 0ull;
#pragma unroll
            for (int k = 0; k < 8; k++) {
                ulonglong2 wv = wcp[k * 1024];
                ulonglong2 uv = uu2[k];
                ay = ffma2(ay, wv.x, uv.x);
                ay = ffma2(ay, wv.y, uv.y);
            }
            float y = hsum2(ay);
            y += __shfl_down_sync(0xffffffffu, y, 4, 8);
            y += __shfl_down_sync(0xffffffffu, y, 2, 8);
            y += __shfl_down_sync(0xffffffffu, y, 1, 8);
            if (q8 == 0) out_b[(size_t)t * OO + r8] = y + bCr;
        }
        // no sync needed here: next Phase A writes only sh_g/sh_v1* (consumed
        // before the Phase-C sync) and reads sh_h/sh_us/sh_fu (synced above).
    }
}

// ---------------- launch ----------------------------------------------------
extern "C" void kernel_launch(void* const* d_in, const int* in_sizes, int n_in,
                              void* d_out, int out_size)
{
    const float* x    = (const float*)d_in[0];   // [32,128,128]
    const float* tsp  = (const float*)d_in[1];   // [32,128]
    const float* tau  = (const float*)d_in[2];   // [256]
    const float* sig  = (const float*)d_in[3];   // [256]
    const float* W_A  = (const float*)d_in[4];   // [256,256]
    const float* W_B  = (const float*)d_in[5];   // [256,128]
    const float* b_B  = (const float*)d_in[6];   // [256]
    const float* W_C  = (const float*)d_in[7];   // [128,256]
    const float* b_C  = (const float*)d_in[8];   // [128]
    const float* W_ih = (const float*)d_in[9];   // [1024,128]
    const float* W_hh = (const float*)d_in[10];  // [1024,256]
    const float* b_ih = (const float*)d_in[11];  // [1024]
    const float* b_hh = (const float*)d_in[12];  // [1024]
    float* out = (float*)d_out;                  // [32,128,128]

    // weight repack (one-time-equivalent, recomputed every call: deterministic)
    pack_weights<<<(G4 * HH + 255) / 256, 256>>>(W_hh, W_A, W_C);

    // xg = x @ W_ih^T + b_ih + b_hh ; Bx = x @ W_B^T + b_B
    gemm_bias<G4, 0><<<dim3(G4 / 64, (BB * TT) / 64), 256>>>(x, W_ih, b_ih, b_hh);
    gemm_bias<HH, 1><<<dim3(HH / 64, (BB * TT) / 64), 256>>>(x, W_B, b_B, nullptr);

    // sequential fused LSTM + closed-form-continuous recurrence
    seq_kernel<<<BB, 1024>>>(tsp, tau, sig, b_C, out);
}

// round 5
// speedup vs baseline: 1.0032x; 1.0032x over previous
#include <cuda_runtime.h>

// Sizes (fixed by the problem)
#define BB   32
#define TT   128
#define INN  128
#define HH   256
#define G4   1024   // 4*HH
#define OO   128

// ---------------- scratch (__device__ globals: no runtime allocation) -------
static __device__ float g_xg[BB * TT * G4];   // xg = x@W_ih^T + b_ih + b_hh   (16.8 MB)
static __device__ float g_bx[BB * TT * HH];   // Bx = x@W_B^T + b_B           (4.2 MB)
static __device__ float g_whh_p[G4 * HH];     // W_hh repacked for coalesced thread-per-row
static __device__ float g_wa_p[HH * HH];      // W_A repacked for (row=tid>>2, quarter=tid&3)
static __device__ float g_wc_p[OO * HH];      // W_C repacked for (row=tid>>3, eighth=tid&7)

typedef unsigned long long ull;

__device__ __forceinline__ ull ffma2(ull c, ull a, ull b) {
    ull d;
    asm("fma.rn.f32x2 %0, %1, %2, %3;" : "=l"(d) : "l"(a), "l"(b), "l"(c));
    return d;
}
__device__ __forceinline__ float hsum2(ull v) {
    return __uint_as_float((unsigned)(v & 0xffffffffull)) +
           __uint_as_float((unsigned)(v >> 32));
}

// ---------------- precompute GEMMs: C[4096,N] = X[4096,128] @ W[N,128]^T + bias (+bias2)
template <int N, int DEST>
__global__ __launch_bounds__(256) void gemm_bias(
    const float* __restrict__ X, const float* __restrict__ W,
    const float* __restrict__ bias, const float* __restrict__ bias2)
{
    constexpr int K = INN;  // 128
    __shared__ float As[32][64];  // k-major
    __shared__ float Bs[32][64];
    float* C = (DEST == 0) ? g_xg : g_bx;

    const int bm = blockIdx.y * 64, bn = blockIdx.x * 64;
    const int tid = threadIdx.x;
    const int tx = tid & 15, ty = tid >> 4;

    float acc[4][4];
#pragma unroll
    for (int r = 0; r < 4; r++)
#pragma unroll
        for (int c = 0; c < 4; c++) acc[r][c] = 0.f;

    for (int k0 = 0; k0 < K; k0 += 32) {
#pragma unroll
        for (int q = 0; q < 2; q++) {
            int i = tid * 2 + q;          // 0..511
            int row = i >> 3;             // 0..63
            int kc = (i & 7) * 4;         // 0..28
            float4 a = *(const float4*)(X + (size_t)(bm + row) * K + k0 + kc);
            As[kc + 0][row] = a.x; As[kc + 1][row] = a.y;
            As[kc + 2][row] = a.z; As[kc + 3][row] = a.w;
            float4 b = *(const float4*)(W + (size_t)(bn + row) * K + k0 + kc);
            Bs[kc + 0][row] = b.x; Bs[kc + 1][row] = b.y;
            Bs[kc + 2][row] = b.z; Bs[kc + 3][row] = b.w;
        }
        __syncthreads();
#pragma unroll
        for (int kk = 0; kk < 32; kk++) {
            float4 av = *(const float4*)&As[kk][ty * 4];
            float4 bv = *(const float4*)&Bs[kk][tx * 4];
            float ar[4] = {av.x, av.y, av.z, av.w};
            float br[4] = {bv.x, bv.y, bv.z, bv.w};
#pragma unroll
            for (int r = 0; r < 4; r++)
#pragma unroll
                for (int c = 0; c < 4; c++) acc[r][c] += ar[r] * br[c];
        }
        __syncthreads();
    }

    float bc[4];
#pragma unroll
    for (int c = 0; c < 4; c++) {
        bc[c] = bias[bn + tx * 4 + c];
        if (bias2) bc[c] += bias2[bn + tx * 4 + c];
    }
#pragma unroll
    for (int r = 0; r < 4; r++) {
        float4 o;
        o.x = acc[r][0] + bc[0]; o.y = acc[r][1] + bc[1];
        o.z = acc[r][2] + bc[2]; o.w = acc[r][3] + bc[3];
        *(float4*)(C + (size_t)(bm + ty * 4 + r) * N + bn + tx * 4) = o;
    }
}

// ---------------- weight repack for coalesced recurrent loads ---------------
// g_whh_p[(k4*1024 + g)*4 + m] = W_hh[g*256 + 4*k4 + m]        (k4: 0..63)
// g_wa_p [(k *1024 + t)*4 + m] = W_A [(t>>2)*256 + (t&3)*64 + 4k + m]  (k: 0..15)
// g_wc_p [(k *1024 + t)*4 + m] = W_C [(t>>3)*256 + (t&7)*32 + 4k + m]  (k: 0..7)
__global__ void pack_weights(const float* __restrict__ W_hh,
                             const float* __restrict__ W_A,
                             const float* __restrict__ W_C)
{
    int i = blockIdx.x * blockDim.x + threadIdx.x;
    if (i < G4 * HH) {
        int m = i & 3, gk = i >> 2;
        int g = gk & 1023, k4 = gk >> 10;
        g_whh_p[i] = W_hh[g * HH + k4 * 4 + m];
    }
    if (i < HH * HH) {
        int m = i & 3, kt = i >> 2;
        int tp = kt & 1023, k = kt >> 10;
        g_wa_p[i] = W_A[(tp >> 2) * HH + (tp & 3) * 64 + k * 4 + m];
    }
    if (i < OO * HH) {
        int m = i & 3, kt = i >> 2;
        int tp = kt & 1023, k = kt >> 10;
        g_wc_p[i] = W_C[(tp >> 3) * HH + (tp & 7) * 32 + k * 4 + m];
    }
}

// ---------------- sequential fused LSTM + CfC kernel: 1 CTA per batch -------
__global__ __launch_bounds__(1024, 1) void seq_kernel(
    const float* __restrict__ timespans,  // [B,T]
    const float* __restrict__ tau,        // [H]
    const float* __restrict__ sigma,      // [H]
    const float* __restrict__ b_C,        // [OUT]
    float* __restrict__ out)              // [B,T,OUT]
{
    __shared__ __align__(16) float sh_h[HH];     // LSTM hidden
    __shared__ __align__(16) float sh_u[HH];     // ODE state
    __shared__ __align__(16) float sh_us[HH];    // u / tau
    __shared__ __align__(16) float sh_fu[HH];    // tanh(u / sigma)
    __shared__ __align__(16) float sh_g[G4];     // gate pre-activations
    __shared__ __align__(16) float sh_v1[HH];    // ts * A_eff @ u
    __shared__ __align__(16) float sh_v1s[HH];   // v1 / tau
    __shared__ __align__(16) float sh_drv[HH];   // W_A @ f_u
    __shared__ __align__(16) float sh_v2[HH];    // A_eff @ v1
    __shared__ __align__(16) float sh_itau[HH];
    __shared__ __align__(16) float sh_isig[HH];

    const int b = blockIdx.x;
    const int tid = threadIdx.x;

    if (tid < HH) {
        sh_h[tid] = 0.f; sh_u[tid] = 0.f; sh_us[tid] = 0.f; sh_fu[tid] = 0.f;
        sh_itau[tid] = 1.0f / tau[tid];
        sh_isig[tid] = 1.0f / sigma[tid];
    }
    float c_st = 0.f;
    __syncthreads();

    const int r4 = tid >> 2, q4 = tid & 3;   // W_A row / quarter of j-range
    const int r8 = tid >> 3, q8 = tid & 7;   // W_C row / eighth of j-range
    const float it_r = sh_itau[r4];
    const float bCr  = b_C[r8];

    const ulonglong2* whh = (const ulonglong2*)g_whh_p + tid;
    const ulonglong2* wap = (const ulonglong2*)g_wa_p + tid;
    const ulonglong2* wcp = (const ulonglong2*)g_wc_p + tid;
    const ulonglong2* hh2 = (const ulonglong2*)sh_h;
    const ulonglong2* us2 = (const ulonglong2*)(sh_us + (q4 << 6));
    const ulonglong2* fu2 = (const ulonglong2*)(sh_fu + (q4 << 6));
    const ulonglong2* v1s2 = (const ulonglong2*)(sh_v1s + (q4 << 6));
    const ulonglong2* uu2 = (const ulonglong2*)(sh_u + (q8 << 5));

    const float* xg_b = g_xg + (size_t)b * TT * G4 + tid;
    const float* bx_b = g_bx + (size_t)b * TT * HH + tid;
    const float* ts_b = timespans + b * TT;
    float* out_b = out + (size_t)b * TT * OO;

    for (int t = 0; t < TT; t++) {
        const float ts = ts_b[t];

        // -------- Phase A: gate pre-activations (all 1024 threads, 1 row each)
        {
            ull a0 = 0ull, a1 = 0ull;
#pragma unroll 4
            for (int k = 0; k < 64; k++) {
                ulonglong2 wv = whh[k * 1024];   // coalesced LDG.128
                ulonglong2 hv = hh2[k];          // broadcast LDS.128
                a0 = ffma2(a0, wv.x, hv.x);
                a1 = ffma2(a1, wv.y, hv.y);
            }
            sh_g[tid] = xg_b[(size_t)t * G4] + hsum2(a0) + hsum2(a1);
        }
        // -------- Phase A2: v1 = ts*A_eff@u and drive = W_A@f_u (shared weight read)
        {
            ull av = 0ull, ad = 0ull;
#pragma unroll
            for (int k = 0; k < 16; k++) {
                ulonglong2 wv = wap[k * 1024];
                ulonglong2 uv = us2[k];
                ulonglong2 fv = fu2[k];
                av = ffma2(av, wv.x, uv.x); av = ffma2(av, wv.y, uv.y);
                ad = ffma2(ad, wv.x, fv.x); ad = ffma2(ad, wv.y, fv.y);
            }
            float v = hsum2(av), d = hsum2(ad);
            v += __shfl_down_sync(0xffffffffu, v, 2, 4);
            v += __shfl_down_sync(0xffffffffu, v, 1, 4);
            d += __shfl_down_sync(0xffffffffu, d, 2, 4);
            d += __shfl_down_sync(0xffffffffu, d, 1, 4);
            if (q4 == 0) {
                float vv = ts * v;
                sh_v1[r4] = vv;
                sh_v1s[r4] = vv * it_r;
                sh_drv[r4] = d;
            }
        }
        __syncthreads();

        // -------- Phase B: LSTM cell update (tid<256) + v2 = A_eff@v1 (all)
        float bb = 0.f;
        if (tid < HH) {
            float gi = sh_g[tid];
            float gf = sh_g[HH + tid];
            float gg = sh_g[2 * HH + tid];
            float go = sh_g[3 * HH + tid];
            float si = 1.f / (1.f + __expf(-gi));
            float sf = 1.f / (1.f + __expf(-gf));
            float so = 1.f / (1.f + __expf(-go));
            c_st = sf * c_st + si * tanhf(gg);
            bb = so * tanhf(c_st);
            sh_h[tid] = bb;
        }
        {
            ull av = 0ull;
#pragma unroll
            for (int k = 0; k < 16; k++) {
                ulonglong2 wv = wap[k * 1024];
                ulonglong2 xv = v1s2[k];
                av = ffma2(av, wv.x, xv.x);
                av = ffma2(av, wv.y, xv.y);
            }
            float v = hsum2(av);
            v += __shfl_down_sync(0xffffffffu, v, 2, 4);
            v += __shfl_down_sync(0xffffffffu, v, 1, 4);
            if (q4 == 0) sh_v2[r4] = v;
        }
        __syncthreads();

        // -------- Phase C: ODE state update (tid<256)
        if (tid < HH) {
            float bx = bx_b[(size_t)t * HH];
            float un = sh_u[tid] + sh_v1[tid] + 0.5f * ts * sh_v2[tid]
                     + ts * (sh_drv[tid] + bx) * sh_itau[tid] + bb;
            sh_u[tid] = un;
            sh_us[tid] = un * sh_itau[tid];
            sh_fu[tid] = tanhf(un * sh_isig[tid]);
        }
        __syncthreads();

        // -------- Phase D: y = u_new @ W_C^T + b_C  (128 rows x 8 lanes)
        {
            ull ay = 0ull;
#pragma unroll
            for (int k = 0; k < 8; k++) {
                ulonglong2 wv = wcp[k * 1024];
                ulonglong2 uv = uu2[k];
                ay = ffma2(ay, wv.x, uv.x);
                ay = ffma2(ay, wv.y, uv.y);
            }
            float y = hsum2(ay);
            y += __shfl_down_sync(0xffffffffu, y, 4, 8);
            y += __shfl_down_sync(0xffffffffu, y, 2, 8);
            y += __shfl_down_sync(0xffffffffu, y, 1, 8);
            if (q8 == 0) out_b[(size_t)t * OO + r8] = y + bCr;
        }
        // no sync needed here: next Phase A writes only sh_g/sh_v1* (consumed
        // before the Phase-C sync) and reads sh_h/sh_us/sh_fu (synced above).
    }
}

// ---------------- launch ----------------------------------------------------
extern "C" void kernel_launch(void* const* d_in, const int* in_sizes, int n_in,
                              void* d_out, int out_size)
{
    const float* x    = (const float*)d_in[0];   // [32,128,128]
    const float* tsp  = (const float*)d_in[1];   // [32,128]
    const float* tau  = (const float*)d_in[2];   // [256]
    const float* sig  = (const float*)d_in[3];   // [256]
    const float* W_A  = (const float*)d_in[4];   // [256,256]
    const float* W_B  = (const float*)d_in[5];   // [256,128]
    const float* b_B  = (const float*)d_in[6];   // [256]
    const float* W_C  = (const float*)d_in[7];   // [128,256]
    const float* b_C  = (const float*)d_in[8];   // [128]
    const float* W_ih = (const float*)d_in[9];   // [1024,128]
    const float* W_hh = (const float*)d_in[10];  // [1024,256]
    const float* b_ih = (const float*)d_in[11];  // [1024]
    const float* b_hh = (const float*)d_in[12];  // [1024]
    float* out = (float*)d_out;                  // [32,128,128]

    // weight repack (one-time-equivalent, recomputed every call: deterministic)
    pack_weights<<<(G4 * HH + 255) / 256, 256>>>(W_hh, W_A, W_C);

    // xg = x @ W_ih^T + b_ih + b_hh ; Bx = x @ W_B^T + b_B
    gemm_bias<G4, 0><<<dim3(G4 / 64, (BB * TT) / 64), 256>>>(x, W_ih, b_ih, b_hh);
    gemm_bias<HH, 1><<<dim3(HH / 64, (BB * TT) / 64), 256>>>(x, W_B, b_B, nullptr);

    // sequential fused LSTM + closed-form-continuous recurrence
    seq_kernel<<<BB, 1024>>>(tsp, tau, sig, b_C, out);
}